// round 4
// baseline (speedup 1.0000x reference)
#include <cuda_runtime.h>
#include <math.h>

#define BS 256
#define T_ 128
#define HID 256
#define G3 768
#define NBG 96
#define Y_OFF 8388608
#define R_OFF 8388864
#define A_OFF 16777472
#define L_OFF 16777728

typedef unsigned long long ull;
union F2 { ull u; float2 f; };
#define FMA2(a,x,y) asm("fma.rn.f32x2 %0,%1,%2,%0;" : "+l"(a) : "l"(x), "l"(y))
__device__ __forceinline__ ull pack2(float v){ ull r; asm("mov.b64 %0,{%1,%1};" : "=l"(r) : "f"(v)); return r; }

__device__ float g_GI0[BS*T_*G3];
__device__ float g_gi1[2][BS*G3];
__device__ float g_h1[2][BS*HID];
__device__ float g_h2[2][BS*HID];
__device__ float g_WC[BS*T_*HID];
__device__ float g_G[BS*T_*HID];
__device__ float g_yg[BS*HID];
__device__ float g_part[(T_-1)*BS];
__device__ unsigned g_cnt;
__device__ unsigned g_gen;

__device__ __forceinline__ float sigm(float x){ return 1.f/(1.f+expf(-x)); }
__device__ __forceinline__ float gelu_f(float x){ return 0.5f*x*(1.f+erff(x*0.70710678118654752f)); }

__device__ __forceinline__ void gbar(unsigned nb){
  __syncthreads();
  if (threadIdx.x==0){
    __threadfence();
    unsigned g = *(volatile unsigned*)&g_gen;
    if (atomicAdd(&g_cnt,1u)==nb-1u){
      g_cnt = 0u;
      __threadfence();
      atomicAdd(&g_gen,1u);
    } else {
      while (*(volatile unsigned*)&g_gen == g) __nanosleep(64);
      __threadfence();
    }
  }
  __syncthreads();
}

// ======== gemm_tc: C[M x N] = act(A[M x 256](lda) @ B[N x 256]^T + bias) ========
// CTA tile 128x128, 512 threads, thread tile 8 rows x 4 cols (cols strided 32)
__global__ void __launch_bounds__(512) gemm_tc(
    const float* __restrict__ A, int lda,
    const float* __restrict__ B,
    const float* __restrict__ bias,
    float* __restrict__ C, int ldc, int act)
{
  __shared__ float sA[32][130];
  __shared__ float sB[32][130];
  const int bm = blockIdx.y*128, bn = blockIdx.x*128;
  const int tid = threadIdx.x;
  const int wg = tid>>5, tx = tid&31;
  const int lrow = tid>>3, lkq = tid&7;   // loader: row 0..63 (+64), kq*4

  ull acc[4][4];
  #pragma unroll
  for (int c=0;c<4;c++){ acc[c][0]=0; acc[c][1]=0; acc[c][2]=0; acc[c][3]=0; }

  float4 pa0 = *(const float4*)(A + (size_t)(bm+lrow)*lda + lkq*4);
  float4 pa1 = *(const float4*)(A + (size_t)(bm+lrow+64)*lda + lkq*4);
  float4 pb0 = *(const float4*)(B + (size_t)(bn+lrow)*256 + lkq*4);
  float4 pb1 = *(const float4*)(B + (size_t)(bn+lrow+64)*256 + lkq*4);

  #pragma unroll 1
  for (int kc=0; kc<256; kc+=32){
    __syncthreads();
    sA[lkq*4+0][lrow]=pa0.x; sA[lkq*4+1][lrow]=pa0.y; sA[lkq*4+2][lrow]=pa0.z; sA[lkq*4+3][lrow]=pa0.w;
    sA[lkq*4+0][lrow+64]=pa1.x; sA[lkq*4+1][lrow+64]=pa1.y; sA[lkq*4+2][lrow+64]=pa1.z; sA[lkq*4+3][lrow+64]=pa1.w;
    sB[lkq*4+0][lrow]=pb0.x; sB[lkq*4+1][lrow]=pb0.y; sB[lkq*4+2][lrow]=pb0.z; sB[lkq*4+3][lrow]=pb0.w;
    sB[lkq*4+0][lrow+64]=pb1.x; sB[lkq*4+1][lrow+64]=pb1.y; sB[lkq*4+2][lrow+64]=pb1.z; sB[lkq*4+3][lrow+64]=pb1.w;
    __syncthreads();
    if (kc+32 < 256){
      pa0 = *(const float4*)(A + (size_t)(bm+lrow)*lda + kc+32 + lkq*4);
      pa1 = *(const float4*)(A + (size_t)(bm+lrow+64)*lda + kc+32 + lkq*4);
      pb0 = *(const float4*)(B + (size_t)(bn+lrow)*256 + kc+32 + lkq*4);
      pb1 = *(const float4*)(B + (size_t)(bn+lrow+64)*256 + kc+32 + lkq*4);
    }
    #pragma unroll
    for (int k=0;k<32;k++){
      ull a0=*(const ull*)&sA[k][wg*8];
      ull a1=*(const ull*)&sA[k][wg*8+2];
      ull a2=*(const ull*)&sA[k][wg*8+4];
      ull a3=*(const ull*)&sA[k][wg*8+6];
      #pragma unroll
      for (int c=0;c<4;c++){
        ull bb = pack2(sB[k][tx+32*c]);
        FMA2(acc[c][0],a0,bb); FMA2(acc[c][1],a1,bb);
        FMA2(acc[c][2],a2,bb); FMA2(acc[c][3],a3,bb);
      }
    }
  }
  #pragma unroll
  for (int c=0;c<4;c++){
    int col = bn + tx + 32*c;
    float bv = bias ? bias[col] : 0.f;
    #pragma unroll
    for (int p=0;p<4;p++){
      F2 u; u.u = acc[c][p];
      float v[2] = {u.f.x, u.f.y};
      #pragma unroll
      for (int h=0;h<2;h++){
        float o = v[h] + bv;
        if (act) o = gelu_f(o);
        size_t r = (size_t)(bm + wg*8 + 2*p + h);
        C[r*ldc + col] = o;
      }
    }
  }
}

// ======== persistent GRU: 96 CTAs x 512 threads, 1 phase/step ========
// grp0: h1(p)@Whh0^T + layer0 update -> h1(p+1)              (p < 128)
// grp1: h1(p)@Wih1^T + bih1 -> gi1[p&1]                      (1 <= p <= 128)
// grp2: h2@Whh1^T + layer1 update -> h2, H[:,p-2,:]          (p >= 2)
__global__ void __launch_bounds__(512,1) gru_kernel(
    const float* __restrict__ Whh0, const float* __restrict__ bhh0,
    const float* __restrict__ Wih1, const float* __restrict__ bih1,
    const float* __restrict__ Whh1, const float* __restrict__ bhh1,
    float* __restrict__ H)
{
  __shared__ float sA[32][68];
  __shared__ ull sB2[32][100];
  const int cta = blockIdx.x, tid = threadIdx.x;
  const int grp = cta/32, loc = cta%32;
  const int rt = loc>>3, ct = loc&7;
  const int wg = tid>>5, tx = tid&31;
  const int row0 = rt*64 + wg*4;
  const int col = ct*32 + tx;
  const bool is0 = (grp==0), is1 = (grp==1), is2 = (grp==2);

  const float* WB = is0 ? Whh0 : (is1 ? Wih1 : Whh1);
  const float* bv = is0 ? bhh0 : (is1 ? bih1 : bhh1);
  const float bR = bv[col], bZ = bv[256+col], bN = bv[512+col];

  const int arow = tid>>3, akq = tid&7;       // A loader: 64 rows x 8 kq
  const int br = tid>>3, bkq = tid&7;         // B loader j0; j1 = +64 rows (tid<256)

  for (int i = cta*512 + tid; i < BS*HID; i += NBG*512){
    g_h1[0][i] = 0.f; g_h2[1][i] = 0.f;
  }
  gbar(NBG);

  #pragma unroll 1
  for (int p=0; p<T_+2; ++p){
    bool active = (is0 && p<T_) || (is1 && p>=1 && p<=T_) || (is2 && p>=2);
    if (active){
      const float* Ain = is2 ? g_h2[(p-1)&1] : g_h1[p&1];

      // epilogue operand prefetch (hidden behind the k-loop)
      float giR[4], giZ[4], giN[4], hold[4];
      if (is0){
        #pragma unroll
        for (int j=0;j<4;j++){
          int b = row0 + j;
          const float* gi = g_GI0 + ((size_t)b*T_ + p)*G3;
          giR[j]=gi[col]; giZ[j]=gi[256+col]; giN[j]=gi[512+col];
          hold[j]=g_h1[p&1][b*HID+col];
        }
      } else if (is2){
        const float* gb = g_gi1[(p-1)&1];
        const float* hb = g_h2[(p-1)&1];
        #pragma unroll
        for (int j=0;j<4;j++){
          int b = row0 + j;
          giR[j]=gb[b*G3+col]; giZ[j]=gb[b*G3+256+col]; giN[j]=gb[b*G3+512+col];
          hold[j]=hb[b*HID+col];
        }
      }

      ull acc[3][2];
      #pragma unroll
      for (int g=0;g<3;g++){ acc[g][0]=0; acc[g][1]=0; }

      float4 pa = *(const float4*)(Ain + (rt*64+arow)*256 + akq*4);
      int g0 = br>>5, rr0 = br&31;
      float4 pb0 = *(const float4*)(WB + (g0*256 + ct*32 + rr0)*256 + bkq*4);
      float4 pb1;
      int g1 = (br+64)>>5, rr1 = (br+64)&31;
      if (tid < 256) pb1 = *(const float4*)(WB + (g1*256 + ct*32 + rr1)*256 + bkq*4);

      #pragma unroll 1
      for (int kc=0;kc<256;kc+=32){
        __syncthreads();
        sA[akq*4+0][arow]=pa.x; sA[akq*4+1][arow]=pa.y; sA[akq*4+2][arow]=pa.z; sA[akq*4+3][arow]=pa.w;
        sB2[bkq*4+0][br]=pack2(pb0.x); sB2[bkq*4+1][br]=pack2(pb0.y);
        sB2[bkq*4+2][br]=pack2(pb0.z); sB2[bkq*4+3][br]=pack2(pb0.w);
        if (tid < 256){
          sB2[bkq*4+0][br+64]=pack2(pb1.x); sB2[bkq*4+1][br+64]=pack2(pb1.y);
          sB2[bkq*4+2][br+64]=pack2(pb1.z); sB2[bkq*4+3][br+64]=pack2(pb1.w);
        }
        __syncthreads();
        if (kc+32 < 256){
          pa = *(const float4*)(Ain + (rt*64+arow)*256 + kc+32 + akq*4);
          pb0 = *(const float4*)(WB + (g0*256 + ct*32 + rr0)*256 + kc+32 + bkq*4);
          if (tid < 256) pb1 = *(const float4*)(WB + (g1*256 + ct*32 + rr1)*256 + kc+32 + bkq*4);
        }
        #pragma unroll
        for (int k=0;k<32;k++){
          ull a0 = *(const ull*)&sA[k][wg*4];
          ull a1 = *(const ull*)&sA[k][wg*4+2];
          #pragma unroll
          for (int g=0;g<3;g++){
            ull b = sB2[k][g*32+tx];
            FMA2(acc[g][0], a0, b);
            FMA2(acc[g][1], a1, b);
          }
        }
      }
      // ---- epilogue ----
      F2 ur0,ur1,uz0,uz1,un0,un1;
      ur0.u=acc[0][0]; ur1.u=acc[0][1];
      uz0.u=acc[1][0]; uz1.u=acc[1][1];
      un0.u=acc[2][0]; un1.u=acc[2][1];
      float fr[4]={ur0.f.x,ur0.f.y,ur1.f.x,ur1.f.y};
      float fz[4]={uz0.f.x,uz0.f.y,uz1.f.x,uz1.f.y};
      float fn[4]={un0.f.x,un0.f.y,un1.f.x,un1.f.y};
      if (is0){
        float* hdst = g_h1[(p+1)&1];
        #pragma unroll
        for (int j=0;j<4;j++){
          int b = row0 + j;
          float r = sigm(giR[j] + fr[j] + bR);
          float z = sigm(giZ[j] + fz[j] + bZ);
          float n = tanhf(giN[j] + r*(fn[j] + bN));
          hdst[b*HID+col] = (1.f-z)*n + z*hold[j];
        }
      } else if (is1){
        float* o = g_gi1[p&1];
        #pragma unroll
        for (int j=0;j<4;j++){
          int b = row0 + j;
          o[b*G3+col]     = fr[j] + bR;
          o[b*G3+256+col] = fz[j] + bZ;
          o[b*G3+512+col] = fn[j] + bN;
        }
      } else {
        float* hdst = g_h2[p&1];
        #pragma unroll
        for (int j=0;j<4;j++){
          int b = row0 + j;
          float r = sigm(giR[j] + fr[j] + bR);
          float z = sigm(giZ[j] + fz[j] + bZ);
          float n = tanhf(giN[j] + r*(fn[j] + bN));
          float hn = (1.f-z)*n + z*hold[j];
          hdst[b*HID+col] = hn;
          H[((size_t)b*T_ + (p-2))*HID + col] = hn;
        }
      }
    }
    gbar(NBG);
  }
}

// ---------------- small heads ----------------
__global__ void y_kernel(const float* __restrict__ Wp2, float* __restrict__ y){
  __shared__ float s[256];
  int b=blockIdx.x, tid=threadIdx.x;
  s[tid] = g_yg[b*256+tid]*Wp2[tid];
  __syncthreads();
  for (int o=128;o;o>>=1){ if(tid<o) s[tid]+=s[tid+o]; __syncthreads(); }
  if(!tid) y[b]=s[0];
}

__global__ void alpha_kernel(const float* __restrict__ P, float* __restrict__ alpha){
  __shared__ float s[256];
  int b=blockIdx.x, tid=threadIdx.x;
  s[tid] = g_WC[((size_t)b*T_+126)*256+tid] * P[((size_t)b*T_+127)*256+tid];
  __syncthreads();
  for (int o=128;o;o>>=1){ if(tid<o) s[tid]+=s[tid+o]; __syncthreads(); }
  if(!tid) alpha[b]=s[0]*(1.f/256.f);
}

__global__ void ce_kernel(const float* __restrict__ P, const int* __restrict__ neg){
  __shared__ float swc[256];
  __shared__ float red[16];
  int b=blockIdx.x, t=blockIdx.y, tid=threadIdx.x;
  int wid=tid>>5, lane=tid&31;
  const float* wc = g_WC + ((size_t)b*T_+t)*HID;
  for (int i=tid;i<256;i+=128) swc[i]=wc[i];
  __syncthreads();
  for (int j=wid;j<16;j+=4){
    int src = (j==0) ? b : neg[((size_t)t*15+(j-1))*BS + b];
    const float* p = P + ((size_t)src*T_ + t + 1)*256;
    float s=0.f;
    for (int d=lane; d<256; d+=32) s += swc[d]*p[d];
    #pragma unroll
    for (int o=16;o;o>>=1) s += __shfl_xor_sync(0xffffffffu, s, o);
    if (!lane) red[j] = s*(1.f/256.f);
  }
  __syncthreads();
  if (!tid){
    float m=red[0];
    #pragma unroll
    for (int j=1;j<16;j++) m=fmaxf(m,red[j]);
    float sum=0.f;
    #pragma unroll
    for (int j=0;j<16;j++) sum+=expf(red[j]-m);
    g_part[(size_t)t*BS+b] = m + logf(sum) - red[0];
  }
}

__global__ void loss_kernel(float* __restrict__ out){
  __shared__ float s[256];
  int tid=threadIdx.x;
  float a=0.f;
  for (int i=tid;i<(T_-1)*BS;i+=256) a+=g_part[i];
  s[tid]=a; __syncthreads();
  for (int o=128;o;o>>=1){ if(tid<o) s[tid]+=s[tid+o]; __syncthreads(); }
  if(!tid) out[0]=s[0]*(1.f/(float)BS);
}

extern "C" void kernel_launch(void* const* d_in, const int* in_sizes, int n_in,
                              void* d_out, int out_size){
  const float *P=(const float*)d_in[0], *Wih0=(const float*)d_in[1], *Whh0=(const float*)d_in[2],
              *bih0=(const float*)d_in[3], *bhh0=(const float*)d_in[4], *Wih1=(const float*)d_in[5],
              *Whh1=(const float*)d_in[6], *bih1=(const float*)d_in[7], *bhh1=(const float*)d_in[8],
              *W=(const float*)d_in[9],  *Wp1=(const float*)d_in[10], *Wp2=(const float*)d_in[11],
              *Wr1=(const float*)d_in[12], *Wr2=(const float*)d_in[13];
  const int* neg=(const int*)d_in[14];
  float* out=(float*)d_out;

  float *pGI0,*pWC,*pG,*pYG;
  cudaGetSymbolAddress((void**)&pGI0, g_GI0);
  cudaGetSymbolAddress((void**)&pWC,  g_WC);
  cudaGetSymbolAddress((void**)&pG,   g_G);
  cudaGetSymbolAddress((void**)&pYG,  g_yg);

  gemm_tc<<<dim3(G3/128, (BS*T_)/128), 512>>>(P, 256, Wih0, bih0, pGI0, G3, 0);
  gru_kernel<<<NBG,512>>>(Whh0,bhh0,Wih1,bih1,Whh1,bhh1,out);
  gemm_tc<<<dim3(2, (BS*T_)/128), 512>>>(out, 256, W,   nullptr, pWC, 256, 0);
  gemm_tc<<<dim3(2, (BS*T_)/128), 512>>>(out, 256, Wr1, nullptr, pG,  256, 1);
  gemm_tc<<<dim3(2, (BS*T_)/128), 512>>>(pG,  256, Wr2, nullptr, out+R_OFF, 256, 0);
  gemm_tc<<<dim3(2, 2), 512>>>(out + 127*HID, T_*HID, Wp1, nullptr, pYG, 256, 1);
  y_kernel<<<BS,256>>>(Wp2, out+Y_OFF);
  alpha_kernel<<<BS,256>>>(P, out+A_OFF);
  ce_kernel<<<dim3(BS, T_-1), 128>>>(P, neg);
  loss_kernel<<<1,256>>>(out+L_OFF);
}

// round 5
// speedup vs baseline: 1.6847x; 1.6847x over previous
#include <cuda_runtime.h>
#include <math.h>

#define BS 256
#define T_ 128
#define HID 256
#define G3 768
#define NBG 96
#define Y_OFF 8388608
#define R_OFF 8388864
#define A_OFF 16777472
#define L_OFF 16777728

#define SMEM_GRU ((96*256 + 2*32*70)*4)

typedef unsigned long long ull;
union F2 { ull u; float2 f; };
#define FMA2(a,x,y) asm("fma.rn.f32x2 %0,%1,%2,%0;" : "+l"(a) : "l"(x), "l"(y))
__device__ __forceinline__ ull pack2(float v){ ull r; asm("mov.b64 %0,{%1,%1};" : "=l"(r) : "f"(v)); return r; }

__device__ float g_GI0[BS*T_*G3];
__device__ float g_gi1[2][BS*G3];
__device__ float g_h1[2][BS*HID];
__device__ float g_h2[2][BS*HID];
__device__ float g_WC[BS*T_*HID];
__device__ float g_G[BS*T_*HID];
__device__ float g_yg[BS*HID];
__device__ float g_part[(T_-1)*BS];
__device__ unsigned g_cnt;
__device__ unsigned g_gen;

__device__ __forceinline__ float sigm(float x){ return 1.f/(1.f+expf(-x)); }
__device__ __forceinline__ float gelu_f(float x){ return 0.5f*x*(1.f+erff(x*0.70710678118654752f)); }

__device__ __forceinline__ void gbar(unsigned nb){
  __syncthreads();
  if (threadIdx.x==0){
    __threadfence();
    unsigned g = *(volatile unsigned*)&g_gen;
    if (atomicAdd(&g_cnt,1u)==nb-1u){
      g_cnt = 0u;
      __threadfence();
      atomicAdd(&g_gen,1u);
    } else {
      while (*(volatile unsigned*)&g_gen == g) __nanosleep(64);
      __threadfence();
    }
  }
  __syncthreads();
}

// ======== gemm_tc: C[M x N] = act(A[M x 256](lda) @ B[N x 256]^T + bias) ========
__global__ void __launch_bounds__(512) gemm_tc(
    const float* __restrict__ A, int lda,
    const float* __restrict__ B,
    const float* __restrict__ bias,
    float* __restrict__ C, int ldc, int act)
{
  __shared__ float sA[32][130];
  __shared__ float sB[32][130];
  const int bm = blockIdx.y*128, bn = blockIdx.x*128;
  const int tid = threadIdx.x;
  const int wg = tid>>5, tx = tid&31;
  const int lrow = tid>>3, lkq = tid&7;

  ull acc[4][4];
  #pragma unroll
  for (int c=0;c<4;c++){ acc[c][0]=0; acc[c][1]=0; acc[c][2]=0; acc[c][3]=0; }

  float4 pa0 = *(const float4*)(A + (size_t)(bm+lrow)*lda + lkq*4);
  float4 pa1 = *(const float4*)(A + (size_t)(bm+lrow+64)*lda + lkq*4);
  float4 pb0 = *(const float4*)(B + (size_t)(bn+lrow)*256 + lkq*4);
  float4 pb1 = *(const float4*)(B + (size_t)(bn+lrow+64)*256 + lkq*4);

  #pragma unroll 1
  for (int kc=0; kc<256; kc+=32){
    __syncthreads();
    sA[lkq*4+0][lrow]=pa0.x; sA[lkq*4+1][lrow]=pa0.y; sA[lkq*4+2][lrow]=pa0.z; sA[lkq*4+3][lrow]=pa0.w;
    sA[lkq*4+0][lrow+64]=pa1.x; sA[lkq*4+1][lrow+64]=pa1.y; sA[lkq*4+2][lrow+64]=pa1.z; sA[lkq*4+3][lrow+64]=pa1.w;
    sB[lkq*4+0][lrow]=pb0.x; sB[lkq*4+1][lrow]=pb0.y; sB[lkq*4+2][lrow]=pb0.z; sB[lkq*4+3][lrow]=pb0.w;
    sB[lkq*4+0][lrow+64]=pb1.x; sB[lkq*4+1][lrow+64]=pb1.y; sB[lkq*4+2][lrow+64]=pb1.z; sB[lkq*4+3][lrow+64]=pb1.w;
    __syncthreads();
    if (kc+32 < 256){
      pa0 = *(const float4*)(A + (size_t)(bm+lrow)*lda + kc+32 + lkq*4);
      pa1 = *(const float4*)(A + (size_t)(bm+lrow+64)*lda + kc+32 + lkq*4);
      pb0 = *(const float4*)(B + (size_t)(bn+lrow)*256 + kc+32 + lkq*4);
      pb1 = *(const float4*)(B + (size_t)(bn+lrow+64)*256 + kc+32 + lkq*4);
    }
    #pragma unroll
    for (int k=0;k<32;k++){
      ull a0=*(const ull*)&sA[k][wg*8];
      ull a1=*(const ull*)&sA[k][wg*8+2];
      ull a2=*(const ull*)&sA[k][wg*8+4];
      ull a3=*(const ull*)&sA[k][wg*8+6];
      #pragma unroll
      for (int c=0;c<4;c++){
        ull bb = pack2(sB[k][tx+32*c]);
        FMA2(acc[c][0],a0,bb); FMA2(acc[c][1],a1,bb);
        FMA2(acc[c][2],a2,bb); FMA2(acc[c][3],a3,bb);
      }
    }
  }
  #pragma unroll
  for (int c=0;c<4;c++){
    int col = bn + tx + 32*c;
    float bv = bias ? bias[col] : 0.f;
    #pragma unroll
    for (int p=0;p<4;p++){
      F2 u; u.u = acc[c][p];
      float v[2] = {u.f.x, u.f.y};
      #pragma unroll
      for (int h=0;h<2;h++){
        float o = v[h] + bv;
        if (act) o = gelu_f(o);
        size_t r = (size_t)(bm + wg*8 + 2*p + h);
        C[r*ldc + col] = o;
      }
    }
  }
}

// ======== persistent GRU: 96 CTAs x 256 threads, weights resident in smem ========
// grp0: h1(p)@Whh0^T + layer0 update -> h1(p+1)      (p < 128)
// grp1: h1(p)@Wih1^T + bih1 -> gi1[p&1]              (1 <= p <= 128)
// grp2: h2@Whh1^T + layer1 update -> h2, H[:,p-2,:]  (p >= 2)
__global__ void __launch_bounds__(256,1) gru_kernel(
    const float* __restrict__ Whh0, const float* __restrict__ bhh0,
    const float* __restrict__ Wih1, const float* __restrict__ bih1,
    const float* __restrict__ Whh1, const float* __restrict__ bhh1,
    float* __restrict__ H)
{
  extern __shared__ float sm[];
  float* wsm = sm;               // [256 k][96 cols] float, row stride 96
  float* sA  = sm + 96*256;      // [2][32 k][row stride 70]

  const int cta = blockIdx.x, tid = threadIdx.x;
  const int grp = cta/32, loc = cta%32;
  const int rt = loc>>3, ct = loc&7;
  const int rg = tid>>4, tx = tid&15;
  const int rg4 = rg*4;
  const int row0 = rt*64 + rg4;       // 4 rows
  const int col2 = ct*32 + tx*2;      // 2 cols
  const bool is0 = (grp==0), is1 = (grp==1), is2 = (grp==2);

  const float* WB = is0 ? Whh0 : (is1 ? Wih1 : Whh1);
  const float* bvp = is0 ? bhh0 : (is1 ? bih1 : bhh1);
  float2 bR = *(const float2*)(bvp+col2);
  float2 bZ = *(const float2*)(bvp+256+col2);
  float2 bN = *(const float2*)(bvp+512+col2);

  const int arow = tid>>2, akq = tid&3;   // A loader

  // one-time weight preload (k-major in smem)
  for (int i = tid; i < 96*64; i += 256){
    int c = i>>6, kq = i&63;
    int g = c>>5, cc = c&31;
    float4 w = *(const float4*)(WB + (size_t)(g*256 + ct*32 + cc)*256 + kq*4);
    wsm[(kq*4+0)*96 + c] = w.x;
    wsm[(kq*4+1)*96 + c] = w.y;
    wsm[(kq*4+2)*96 + c] = w.z;
    wsm[(kq*4+3)*96 + c] = w.w;
  }
  for (int i = cta*256 + tid; i < BS*HID; i += NBG*256){
    g_h1[0][i] = 0.f; g_h2[1][i] = 0.f;
  }
  gbar(NBG);

  #pragma unroll 1
  for (int p=0; p<T_+2; ++p){
    bool active = (is0 && p<T_) || (is1 && p>=1 && p<=T_) || (is2 && p>=2);
    if (active){
      const float* Ain = is2 ? g_h2[(p-1)&1] : g_h1[p&1];

      // epilogue operand prefetch
      float2 gR[4], gZ[4], gN[4], hold[4];
      if (is0){
        #pragma unroll
        for (int j=0;j<4;j++){
          const float* gi = g_GI0 + ((size_t)(row0+j)*T_ + p)*G3;
          gR[j]=*(const float2*)(gi+col2); gZ[j]=*(const float2*)(gi+256+col2); gN[j]=*(const float2*)(gi+512+col2);
          hold[j]=*(const float2*)(g_h1[p&1]+(row0+j)*HID+col2);
        }
      } else if (is2){
        const float* gb = g_gi1[(p-1)&1];
        const float* hb = g_h2[(p-1)&1];
        #pragma unroll
        for (int j=0;j<4;j++){
          const float* gi = gb + (size_t)(row0+j)*G3;
          gR[j]=*(const float2*)(gi+col2); gZ[j]=*(const float2*)(gi+256+col2); gN[j]=*(const float2*)(gi+512+col2);
          hold[j]=*(const float2*)(hb+(row0+j)*HID+col2);
        }
      }

      ull acc[3][2][2];
      #pragma unroll
      for (int g=0;g<3;g++){ acc[g][0][0]=0; acc[g][0][1]=0; acc[g][1][0]=0; acc[g][1][1]=0; }

      // chunk 0 load + store
      const float* arp = Ain + (size_t)(rt*64+arow)*256;
      float4 pa0 = *(const float4*)(arp + akq*4);
      float4 pa1 = *(const float4*)(arp + (akq+4)*4);
      {
        float* d0 = sA + (akq*4)*70 + arow;
        float* d1 = sA + ((akq+4)*4)*70 + arow;
        d0[0]=pa0.x; d0[70]=pa0.y; d0[140]=pa0.z; d0[210]=pa0.w;
        d1[0]=pa1.x; d1[70]=pa1.y; d1[140]=pa1.z; d1[210]=pa1.w;
      }
      __syncthreads();

      #pragma unroll 1
      for (int kc=0; kc<8; kc++){
        const float* sAc = sA + (kc&1)*2240;
        if (kc<7){
          pa0 = *(const float4*)(arp + (kc+1)*32 + akq*4);
          pa1 = *(const float4*)(arp + (kc+1)*32 + (akq+4)*4);
        }
        const float* wkb = wsm + (kc*32)*96;
        #pragma unroll
        for (int k=0;k<32;k++){
          ull a01 = *(const ull*)(sAc + k*70 + rg4);
          ull a23 = *(const ull*)(sAc + k*70 + rg4 + 2);
          const float* bk = wkb + k*96 + tx*2;
          float2 b0 = *(const float2*)(bk);
          float2 b1 = *(const float2*)(bk+32);
          float2 b2 = *(const float2*)(bk+64);
          ull q;
          q = pack2(b0.x); FMA2(acc[0][0][0],a01,q); FMA2(acc[0][0][1],a23,q);
          q = pack2(b0.y); FMA2(acc[0][1][0],a01,q); FMA2(acc[0][1][1],a23,q);
          q = pack2(b1.x); FMA2(acc[1][0][0],a01,q); FMA2(acc[1][0][1],a23,q);
          q = pack2(b1.y); FMA2(acc[1][1][0],a01,q); FMA2(acc[1][1][1],a23,q);
          q = pack2(b2.x); FMA2(acc[2][0][0],a01,q); FMA2(acc[2][0][1],a23,q);
          q = pack2(b2.y); FMA2(acc[2][1][0],a01,q); FMA2(acc[2][1][1],a23,q);
        }
        if (kc<7){
          float* buf1 = sA + ((kc+1)&1)*2240;
          float* d0 = buf1 + (akq*4)*70 + arow;
          float* d1 = buf1 + ((akq+4)*4)*70 + arow;
          d0[0]=pa0.x; d0[70]=pa0.y; d0[140]=pa0.z; d0[210]=pa0.w;
          d1[0]=pa1.x; d1[70]=pa1.y; d1[140]=pa1.z; d1[210]=pa1.w;
          __syncthreads();
        }
      }

      // ---- epilogue (row j = row0+j; pr=j>>1, h=j&1) ----
      #pragma unroll
      for (int j=0;j<4;j++){
        int pr = j>>1, h = j&1;
        F2 ur,uz,un, ur2,uz2,un2;
        ur.u=acc[0][0][pr]; uz.u=acc[1][0][pr]; un.u=acc[2][0][pr];
        ur2.u=acc[0][1][pr]; uz2.u=acc[1][1][pr]; un2.u=acc[2][1][pr];
        float frx = h? ur.f.y:ur.f.x,  fry = h? ur2.f.y:ur2.f.x;
        float fzx = h? uz.f.y:uz.f.x,  fzy = h? uz2.f.y:uz2.f.x;
        float fnx = h? un.f.y:un.f.x,  fny = h? un2.f.y:un2.f.x;
        int b = row0 + j;
        if (is0){
          float r0 = sigm(gR[j].x + frx + bR.x), r1 = sigm(gR[j].y + fry + bR.y);
          float z0 = sigm(gZ[j].x + fzx + bZ.x), z1 = sigm(gZ[j].y + fzy + bZ.y);
          float n0 = tanhf(gN[j].x + r0*(fnx + bN.x)), n1 = tanhf(gN[j].y + r1*(fny + bN.y));
          float2 o; o.x = (1.f-z0)*n0 + z0*hold[j].x; o.y = (1.f-z1)*n1 + z1*hold[j].y;
          *(float2*)(g_h1[(p+1)&1] + b*HID + col2) = o;
        } else if (is1){
          float* og = g_gi1[p&1] + (size_t)b*G3;
          float2 o;
          o.x = frx + bR.x; o.y = fry + bR.y; *(float2*)(og+col2) = o;
          o.x = fzx + bZ.x; o.y = fzy + bZ.y; *(float2*)(og+256+col2) = o;
          o.x = fnx + bN.x; o.y = fny + bN.y; *(float2*)(og+512+col2) = o;
        } else {
          float r0 = sigm(gR[j].x + frx + bR.x), r1 = sigm(gR[j].y + fry + bR.y);
          float z0 = sigm(gZ[j].x + fzx + bZ.x), z1 = sigm(gZ[j].y + fzy + bZ.y);
          float n0 = tanhf(gN[j].x + r0*(fnx + bN.x)), n1 = tanhf(gN[j].y + r1*(fny + bN.y));
          float2 o; o.x = (1.f-z0)*n0 + z0*hold[j].x; o.y = (1.f-z1)*n1 + z1*hold[j].y;
          *(float2*)(g_h2[p&1] + b*HID + col2) = o;
          *(float2*)(H + ((size_t)b*T_ + (p-2))*HID + col2) = o;
        }
      }
    }
    gbar(NBG);
  }
}

// ---------------- small heads ----------------
__global__ void y_kernel(const float* __restrict__ Wp2, float* __restrict__ y){
  __shared__ float s[256];
  int b=blockIdx.x, tid=threadIdx.x;
  s[tid] = g_yg[b*256+tid]*Wp2[tid];
  __syncthreads();
  for (int o=128;o;o>>=1){ if(tid<o) s[tid]+=s[tid+o]; __syncthreads(); }
  if(!tid) y[b]=s[0];
}

__global__ void alpha_kernel(const float* __restrict__ P, float* __restrict__ alpha){
  __shared__ float s[256];
  int b=blockIdx.x, tid=threadIdx.x;
  s[tid] = g_WC[((size_t)b*T_+126)*256+tid] * P[((size_t)b*T_+127)*256+tid];
  __syncthreads();
  for (int o=128;o;o>>=1){ if(tid<o) s[tid]+=s[tid+o]; __syncthreads(); }
  if(!tid) alpha[b]=s[0]*(1.f/256.f);
}

__global__ void ce_kernel(const float* __restrict__ P, const int* __restrict__ neg){
  __shared__ float swc[256];
  __shared__ float red[16];
  int b=blockIdx.x, t=blockIdx.y, tid=threadIdx.x;
  int wid=tid>>5, lane=tid&31;
  const float* wc = g_WC + ((size_t)b*T_+t)*HID;
  for (int i=tid;i<256;i+=128) swc[i]=wc[i];
  __syncthreads();
  for (int j=wid;j<16;j+=4){
    int src = (j==0) ? b : neg[((size_t)t*15+(j-1))*BS + b];
    const float* p = P + ((size_t)src*T_ + t + 1)*256;
    float s=0.f;
    for (int d=lane; d<256; d+=32) s += swc[d]*p[d];
    #pragma unroll
    for (int o=16;o;o>>=1) s += __shfl_xor_sync(0xffffffffu, s, o);
    if (!lane) red[j] = s*(1.f/256.f);
  }
  __syncthreads();
  if (!tid){
    float m=red[0];
    #pragma unroll
    for (int j=1;j<16;j++) m=fmaxf(m,red[j]);
    float sum=0.f;
    #pragma unroll
    for (int j=0;j<16;j++) sum+=expf(red[j]-m);
    g_part[(size_t)t*BS+b] = m + logf(sum) - red[0];
  }
}

__global__ void loss_kernel(float* __restrict__ out){
  __shared__ float s[256];
  int tid=threadIdx.x;
  float a=0.f;
  for (int i=tid;i<(T_-1)*BS;i+=256) a+=g_part[i];
  s[tid]=a; __syncthreads();
  for (int o=128;o;o>>=1){ if(tid<o) s[tid]+=s[tid+o]; __syncthreads(); }
  if(!tid) out[0]=s[0]*(1.f/(float)BS);
}

extern "C" void kernel_launch(void* const* d_in, const int* in_sizes, int n_in,
                              void* d_out, int out_size){
  const float *P=(const float*)d_in[0], *Wih0=(const float*)d_in[1], *Whh0=(const float*)d_in[2],
              *bih0=(const float*)d_in[3], *bhh0=(const float*)d_in[4], *Wih1=(const float*)d_in[5],
              *Whh1=(const float*)d_in[6], *bih1=(const float*)d_in[7], *bhh1=(const float*)d_in[8],
              *W=(const float*)d_in[9],  *Wp1=(const float*)d_in[10], *Wp2=(const float*)d_in[11],
              *Wr1=(const float*)d_in[12], *Wr2=(const float*)d_in[13];
  const int* neg=(const int*)d_in[14];
  float* out=(float*)d_out;

  float *pGI0,*pWC,*pG,*pYG;
  cudaGetSymbolAddress((void**)&pGI0, g_GI0);
  cudaGetSymbolAddress((void**)&pWC,  g_WC);
  cudaGetSymbolAddress((void**)&pG,   g_G);
  cudaGetSymbolAddress((void**)&pYG,  g_yg);

  cudaFuncSetAttribute(gru_kernel, cudaFuncAttributeMaxDynamicSharedMemorySize, SMEM_GRU);

  gemm_tc<<<dim3(G3/128, (BS*T_)/128), 512>>>(P, 256, Wih0, bih0, pGI0, G3, 0);
  gru_kernel<<<NBG, 256, SMEM_GRU>>>(Whh0,bhh0,Wih1,bih1,Whh1,bhh1,out);
  gemm_tc<<<dim3(2, (BS*T_)/128), 512>>>(out, 256, W,   nullptr, pWC, 256, 0);
  gemm_tc<<<dim3(2, (BS*T_)/128), 512>>>(out, 256, Wr1, nullptr, pG,  256, 1);
  gemm_tc<<<dim3(2, (BS*T_)/128), 512>>>(pG,  256, Wr2, nullptr, out+R_OFF, 256, 0);
  gemm_tc<<<dim3(2, 2), 512>>>(out + 127*HID, T_*HID, Wp1, nullptr, pYG, 256, 1);
  y_kernel<<<BS,256>>>(Wp2, out+Y_OFF);
  alpha_kernel<<<BS,256>>>(P, out+A_OFF);
  ce_kernel<<<dim3(BS, T_-1), 128>>>(P, neg);
  loss_kernel<<<1,256>>>(out+L_OFF);
}